// round 14
// baseline (speedup 1.0000x reference)
#include <cuda_runtime.h>
#include <cuda_fp16.h>
#include <cstdint>

#define BSZ 2
#define SEQ 2048
#define HID 1024
#define NS  4
#define H   256

// ---------------- device scratch ----------------
__device__ __align__(256) __half g_hidH [BSZ*SEQ*HID];   // hidden hi, row-major
__device__ __align__(256) __half g_hidTH[BSZ*HID*SEQ];   // hidden hi, transposed
__device__ __align__(256) __half g_qH   [NS*H*HID];      // queries hi
__device__ __align__(256) __half g_cTH  [NS*H*HID];      // combiners^T hi
__device__ __align__(256) float  g_Pf   [8*H*H];         // Xh^T Xh (upper 128-tiles)
__device__ __align__(256) __half g_tmpH [8*H*HID];
__device__ __align__(256) float  g_Mf   [2*8*H*H];       // M^T split-K partials (x2)

// ---------------- helpers ----------------
__device__ __forceinline__ uint32_t smem_u32(const void* p) {
    uint32_t a;
    asm("{ .reg .u64 t; cvta.to.shared.u64 t, %1; cvt.u32.u64 %0, t; }" : "=r"(a) : "l"(p));
    return a;
}
__device__ __forceinline__ void cpa(uint32_t dst, const void* src) {
    asm volatile("cp.async.cg.shared.global [%0], [%1], 16;" :: "r"(dst), "l"(src));
}
__device__ __forceinline__ void ldsm4(uint32_t (&r)[4], uint32_t addr) {
    asm volatile("ldmatrix.sync.aligned.m8n8.x4.shared.b16 {%0,%1,%2,%3}, [%4];"
        : "=r"(r[0]), "=r"(r[1]), "=r"(r[2]), "=r"(r[3]) : "r"(addr));
}
__device__ __forceinline__ void sts128(uint32_t addr, uint32_t x, uint32_t y,
                                       uint32_t z, uint32_t w) {
    asm volatile("st.shared.v4.b32 [%0], {%1, %2, %3, %4};"
        :: "r"(addr), "r"(x), "r"(y), "r"(z), "r"(w) : "memory");
}
__device__ __forceinline__ void mma16816(float (&d)[4], const uint32_t (&a)[4],
                                         uint32_t b0, uint32_t b1) {
    asm volatile("mma.sync.aligned.m16n8k16.row.col.f32.f16.f16.f32 "
        "{%0,%1,%2,%3}, {%4,%5,%6,%7}, {%8,%9}, {%0,%1,%2,%3};"
        : "+f"(d[0]), "+f"(d[1]), "+f"(d[2]), "+f"(d[3])
        : "r"(a[0]), "r"(a[1]), "r"(a[2]), "r"(a[3]), "r"(b0), "r"(b1));
}
__device__ __forceinline__ uint32_t swz(int row, int c) {
    return (uint32_t)(row * 64 + ((c ^ ((row >> 1) & 3)) << 4));
}

// Stage layout: Ah[128x32] @0 (8KB), B[NTILE x 32] fp16 after
template<int NTILE> struct Lay {
    static constexpr uint32_t BH = 8192u;
    static constexpr uint32_t BN = (NTILE == 128) ? 8192u : 4096u;
    static constexpr uint32_t STAGE = BH + BN;
};

// A-only cp.async stage load (A[128 x 32] fp16)
__device__ __forceinline__ void load_stageA(uint32_t sb,
        const __half* __restrict__ Ah, int lda, int k0) {
    int tid = threadIdx.x;
    #pragma unroll
    for (int t = 0; t < 2; ++t) {
        int cid = tid + t * 256;
        int row = cid >> 2, c = cid & 3;
        cpa(sb + swz(row, c), Ah + (size_t)row * lda + k0 + c * 8);
    }
    asm volatile("cp.async.commit_group;" ::: "memory");
}
// A+B cp.async stage load (B fp16 source)
template<int NTILE>
__device__ __forceinline__ void load_stageAB(uint32_t sb,
        const __half* __restrict__ Ah, int lda,
        const __half* __restrict__ Bh, int ldb, int k0) {
    using L = Lay<NTILE>;
    int tid = threadIdx.x;
    #pragma unroll
    for (int t = 0; t < 2; ++t) {
        int cid = tid + t * 256;
        int row = cid >> 2, c = cid & 3;
        cpa(sb + swz(row, c), Ah + (size_t)row * lda + k0 + c * 8);
    }
    if (NTILE == 128) {
        #pragma unroll
        for (int t = 0; t < 2; ++t) {
            int cid = tid + t * 256;
            int row = cid >> 2, c = cid & 3;
            cpa(sb + L::BH + swz(row, c), Bh + (size_t)row * ldb + k0 + c * 8);
        }
    } else {
        int row = tid >> 2, c = tid & 3;
        cpa(sb + L::BH + swz(row, c), Bh + (size_t)row * ldb + k0 + c * 8);
    }
    asm volatile("cp.async.commit_group;" ::: "memory");
}

// fp32 B gather into regs. MIRROR: symmetric source (upper 128-tiles stored).
// Bf2 (non-mirror only): second split-K partial to sum.
template<int NTILE, bool MIRROR>
__device__ __forceinline__ void ldgB(float* rB, const float* __restrict__ Bf,
                                     const float* __restrict__ Bf2,
                                     int n0g, int kg0) {
    int tid = threadIdx.x;
    #pragma unroll
    for (int t = 0; t < NTILE / 64; ++t) {
        int cid = tid + t * 256;
        int r = cid >> 2, c = cid & 3;
        int gn = n0g + r, gk = kg0 + c * 8;
        float* d = rB + t * 8;
        if (MIRROR && (gn >> 7) > (gk >> 7)) {
            #pragma unroll
            for (int j = 0; j < 8; ++j)
                d[j] = Bf[(size_t)(gk + j) * H + gn];
        } else {
            size_t off = (size_t)gn * H + gk;
            float4 v0 = *reinterpret_cast<const float4*>(Bf + off);
            float4 v1 = *reinterpret_cast<const float4*>(Bf + off + 4);
            if (!MIRROR && Bf2 != nullptr) {
                float4 w0 = *reinterpret_cast<const float4*>(Bf2 + off);
                float4 w1 = *reinterpret_cast<const float4*>(Bf2 + off + 4);
                v0.x += w0.x; v0.y += w0.y; v0.z += w0.z; v0.w += w0.w;
                v1.x += w1.x; v1.y += w1.y; v1.z += w1.z; v1.w += w1.w;
            }
            *reinterpret_cast<float4*>(d)     = v0;
            *reinterpret_cast<float4*>(d + 4) = v1;
        }
    }
}
// convert + store B regs into swizzled fp16 stage region (shared-space store)
template<int NTILE>
__device__ __forceinline__ void stsB(uint32_t sbB, const float* rB) {
    int tid = threadIdx.x;
    #pragma unroll
    for (int t = 0; t < NTILE / 64; ++t) {
        int cid = tid + t * 256;
        int r = cid >> 2, c = cid & 3;
        const float* s = rB + t * 8;
        __half2 h0, h1, h2, h3;
        h0.x = __float2half_rn(s[0]); h0.y = __float2half_rn(s[1]);
        h1.x = __float2half_rn(s[2]); h1.y = __float2half_rn(s[3]);
        h2.x = __float2half_rn(s[4]); h2.y = __float2half_rn(s[5]);
        h3.x = __float2half_rn(s[6]); h3.y = __float2half_rn(s[7]);
        sts128(sbB + swz(r, c),
               *reinterpret_cast<uint32_t*>(&h0),
               *reinterpret_cast<uint32_t*>(&h1),
               *reinterpret_cast<uint32_t*>(&h2),
               *reinterpret_cast<uint32_t*>(&h3));
    }
}

// C[128,NTILE] = Ah[128,K] * B[NTILE,K]^T   (fp16, fp32 accum)
// BSRC: 0 = B fp16 cp.async; 1 = B fp32 convert (+optional partial sum Bf2);
//       2 = fp32 convert + sym mirror
// EPI:  0 = atomicAdd fp32, 1 = store fp32, 2 = store fp16
template<int EPI, int NTILE, int BSRC>
__device__ void gemm_mma(const __half* Ah, int lda,
                         const __half* Bh, int ldb,
                         const float* Bf, const float* Bf2, int n0g, int kIters,
                         float* Cf, __half* CH, int ldc) {
    using L = Lay<NTILE>;
    constexpr int MI = (NTILE == 128) ? 4 : 2;
    extern __shared__ char smem[];
    const uint32_t sbase = smem_u32(smem);
    const int tid = threadIdx.x, lane = tid & 31, wid = tid >> 5;
    const int wm = (NTILE == 128) ? (wid & 1) : (wid & 3);
    const int wn = (NTILE == 128) ? (wid >> 1) : (wid >> 2);

    float acc[MI][4][4];
    #pragma unroll
    for (int i = 0; i < MI; ++i)
        #pragma unroll
        for (int j = 0; j < 4; ++j)
            #pragma unroll
            for (int v = 0; v < 4; ++v) acc[i][j][v] = 0.f;

    float rB[(BSRC == 0) ? 1 : (NTILE / 64) * 8];
    if (BSRC == 0) {
        load_stageAB<NTILE>(sbase,            Ah, lda, Bh, ldb, 0);
        load_stageAB<NTILE>(sbase + L::STAGE, Ah, lda, Bh, ldb, 32);
    } else {
        load_stageA(sbase,            Ah, lda, 0);
        load_stageA(sbase + L::STAGE, Ah, lda, 32);
        ldgB<NTILE, BSRC == 2>(rB, Bf, Bf2, n0g, 0);
    }

    const int mi = lane >> 3, lr = lane & 7;
    const int rA0 = wm * (MI * 16) + (mi & 1) * 8 + lr;
    const int rB0 = wn * 32 + (mi & 1) * 8 + lr;
    const int chb = mi >> 1;

    for (int it = 0; it < kIters; ++it) {
        if (it + 1 < kIters)
            asm volatile("cp.async.wait_group 1;" ::: "memory");
        else
            asm volatile("cp.async.wait_group 0;" ::: "memory");
        uint32_t sb = sbase + (uint32_t)(it % 3) * L::STAGE;
        if (BSRC != 0)
            stsB<NTILE>(sb + L::BH, rB);
        __syncthreads();

        if (it + 2 < kIters) {
            if (BSRC == 0)
                load_stageAB<NTILE>(sbase + (uint32_t)((it + 2) % 3) * L::STAGE,
                                    Ah, lda, Bh, ldb, (it + 2) * 32);
            else
                load_stageA(sbase + (uint32_t)((it + 2) % 3) * L::STAGE,
                            Ah, lda, (it + 2) * 32);
        }
        if (BSRC != 0 && it + 1 < kIters)
            ldgB<NTILE, BSRC == 2>(rB, Bf, Bf2, n0g, (it + 1) * 32);

        #pragma unroll
        for (int kk = 0; kk < 2; ++kk) {
            int c = kk * 2 + chb;
            uint32_t a[MI][4], bfr[2][4];
            #pragma unroll
            for (int j = 0; j < 2; ++j) {
                int r = rB0 + j * 16;
                ldsm4(bfr[j], sb + L::BH + swz(r, c));
            }
            #pragma unroll
            for (int i = 0; i < MI; ++i) {
                int r = rA0 + i * 16;
                ldsm4(a[i], sb + swz(r, c));
            }
            #pragma unroll
            for (int i = 0; i < MI; ++i)
                #pragma unroll
                for (int j = 0; j < 4; ++j) {
                    int j2 = j >> 1, jo = j & 1;
                    mma16816(acc[i][j], a[i], bfr[j2][jo], bfr[j2][jo + 2]);
                }
        }
    }

    #pragma unroll
    for (int i = 0; i < MI; ++i)
        #pragma unroll
        for (int j = 0; j < 4; ++j) {
            int r   = wm * (MI * 16) + i * 16 + (lane >> 2);
            int col = wn * 32 + j * 8 + (lane & 3) * 2;
            if (EPI == 0) {
                atomicAdd(Cf + (size_t)r * ldc + col,           acc[i][j][0]);
                atomicAdd(Cf + (size_t)r * ldc + col + 1,       acc[i][j][1]);
                atomicAdd(Cf + (size_t)(r + 8) * ldc + col,     acc[i][j][2]);
                atomicAdd(Cf + (size_t)(r + 8) * ldc + col + 1, acc[i][j][3]);
            } else if (EPI == 1) {
                *reinterpret_cast<float2*>(Cf + (size_t)r * ldc + col) =
                    make_float2(acc[i][j][0], acc[i][j][1]);
                *reinterpret_cast<float2*>(Cf + (size_t)(r + 8) * ldc + col) =
                    make_float2(acc[i][j][2], acc[i][j][3]);
            } else {
                __half2 p0, p1;
                p0.x = __float2half_rn(acc[i][j][0]);
                p0.y = __float2half_rn(acc[i][j][1]);
                p1.x = __float2half_rn(acc[i][j][2]);
                p1.y = __float2half_rn(acc[i][j][3]);
                *reinterpret_cast<__half2*>(CH + (size_t)r * ldc + col)       = p0;
                *reinterpret_cast<__half2*>(CH + (size_t)(r + 8) * ldc + col) = p1;
            }
        }
}

// ---- pass wrappers ----
// p1: P = Xh^T Xh, 3 live tiles, split-K x8 over t (atomic)
__global__ void __launch_bounds__(256, 2) k_p1() {
    int z = blockIdx.z, pair = z >> 3, split = z & 7;
    int m0 = (blockIdx.x == 2) ? 128 : 0;
    int n0 = (blockIdx.x == 0) ? 0 : 128;
    int b = pair >> 2, q = pair & 3;
    size_t base = ((size_t)b * HID + q * H) * SEQ + split * 256;
    const __half* A = g_hidTH + base + (size_t)m0 * SEQ;
    const __half* B = g_hidTH + base + (size_t)n0 * SEQ;
    gemm_mma<0, 128, 0>(A, SEQ, B, SEQ, nullptr, nullptr, 0, 8,
                        g_Pf + (size_t)pair * H * H + m0 * H + n0, nullptr, H);
}
// p2: tmp = qw_h * K  (K = sym(P), fp32 source w/ fused mirror+convert)
__global__ void __launch_bounds__(256, 2) k_p2() {
    int z = blockIdx.z, b = z >> 4, a = (z >> 2) & 3, q = z & 3;
    int m0 = blockIdx.x * 128, n0 = blockIdx.y * 64;
    size_t ab = (size_t)a * H * HID + (size_t)m0 * HID + q * H;
    size_t cb = (size_t)((b << 2) | a) * H * HID + (size_t)m0 * HID + q * H + n0;
    const float* Bf = g_Pf + (size_t)((b << 2) | q) * H * H;
    gemm_mma<2, 64, 2>(g_qH + ab, HID, nullptr, 0, Bf, nullptr, n0, 8,
                       nullptr, g_tmpH + cb, HID);
}
// p3: M^T partials = cT_h * tmpH^T, split-K x2, plain stores (no atomics)
__global__ void __launch_bounds__(256, 2) k_p3() {
    int z = blockIdx.z, pair = z >> 1, split = z & 1;
    int a = pair & 3;
    int m0 = blockIdx.x * 128, n0 = blockIdx.y * 64;
    size_t ab = (size_t)a * H * HID + (size_t)m0 * HID + split * 512;
    size_t bb = (size_t)pair * H * HID + (size_t)n0 * HID + split * 512;
    float* dst = g_Mf + (size_t)split * 8 * H * H + (size_t)pair * H * H + m0 * H + n0;
    gemm_mma<1, 64, 0>(g_cTH + ab, HID, g_tmpH + bb, HID, nullptr, nullptr, 0, 16,
                       dst, nullptr, H);
}
// p4: out = hid_h * M  (M = partial0 + partial1, fused sum + convert)
__global__ void __launch_bounds__(256, 2) k_p4(float* __restrict__ out) {
    int pair = blockIdx.z, b = pair >> 2, a = pair & 3;
    int m0 = blockIdx.x * 128, n0 = blockIdx.y * 128;
    size_t ab = (size_t)b * SEQ * HID + (size_t)m0 * HID + a * H;
    const float* Bf  = g_Mf + (size_t)pair * H * H;
    const float* Bf2 = g_Mf + (size_t)8 * H * H + (size_t)pair * H * H;
    gemm_mma<1, 128, 1>(g_hidH + ab, HID, nullptr, 0, Bf, Bf2, n0, 8,
                        out + ab + n0, nullptr, HID);
}

// ---- merged prep ----
// [0,1024): hidden convert + transpose; [1024,2048): queries; [2048,3072): comb T;
// [3072,3200): zero Pf
__global__ void __launch_bounds__(256) k_prep(const float* __restrict__ hid,
                                              const float* __restrict__ q,
                                              const float* __restrict__ c) {
    int blk = blockIdx.x, tid = threadIdx.x;
    if (blk < 1024) {
        __shared__ __half shH[64][65];
        int b = blk >> 9, tt = (blk >> 4) & 31, ft = blk & 15;
        int w = tid >> 5, l = tid & 31;
        int t0 = tt * 64, f0 = ft * 64;
        #pragma unroll
        for (int i = 0; i < 8; ++i) {
            int r = w * 8 + i;
            size_t gi = ((size_t)b * SEQ + t0 + r) * HID + f0 + l * 2;
            float2 v = *reinterpret_cast<const float2*>(hid + gi);
            __half h0 = __float2half_rn(v.x), h1 = __float2half_rn(v.y);
            shH[r][l * 2] = h0; shH[r][l * 2 + 1] = h1;
            __half2 ph; ph.x = h0; ph.y = h1;
            *reinterpret_cast<__half2*>(g_hidH + gi) = ph;
        }
        __syncthreads();
        #pragma unroll
        for (int i = 0; i < 8; ++i) {
            int fr = w * 8 + i;
            size_t gi = ((size_t)b * HID + f0 + fr) * SEQ + t0 + l * 2;
            __half2 hv;
            hv.x = shH[l * 2][fr]; hv.y = shH[l * 2 + 1][fr];
            *reinterpret_cast<__half2*>(g_hidTH + gi) = hv;
        }
    } else if (blk < 2048) {
        size_t i = (size_t)(blk - 1024) * 1024 + tid * 4;
        float4 v = *reinterpret_cast<const float4*>(q + i);
        __half2 p0, p1;
        p0.x = __float2half_rn(v.x); p0.y = __float2half_rn(v.y);
        p1.x = __float2half_rn(v.z); p1.y = __float2half_rn(v.w);
        *reinterpret_cast<__half2*>(g_qH + i)     = p0;
        *reinterpret_cast<__half2*>(g_qH + i + 2) = p1;
    } else if (blk < 3072) {
        __shared__ __half sh[32][33];
        int z = blk - 2048;
        int a = z >> 8, kt = (z >> 3) & 31, gt = z & 7;
        int tx = tid & 31, ty = tid >> 5;
        int k0 = kt * 32, g0 = gt * 32;
        #pragma unroll
        for (int i = 0; i < 4; ++i) {
            int r = ty + i * 8;
            sh[r][tx] = __float2half_rn(c[((size_t)a * HID + k0 + r) * H + g0 + tx]);
        }
        __syncthreads();
        #pragma unroll
        for (int i = 0; i < 4; ++i) {
            int r = ty + i * 8;
            g_cTH[((size_t)a * H + g0 + r) * HID + k0 + tx] = sh[tx][r];
        }
    } else {
        int z = blk - 3072;                 // 0..127 : zero Pf only
        size_t base = (size_t)z * 4096 + tid * 16;
        float4 zv = make_float4(0.f, 0.f, 0.f, 0.f);
        #pragma unroll
        for (int i = 0; i < 4; ++i)
            *reinterpret_cast<float4*>(g_Pf + base + i * 4) = zv;
    }
}

extern "C" void kernel_launch(void* const* d_in, const int* in_sizes, int n_in,
                              void* d_out, int out_size) {
    const float* hidden    = (const float*)d_in[0];
    const float* queries   = (const float*)d_in[1];
    const float* combiners = (const float*)d_in[2];
    float* out = (float*)d_out;

    cudaFuncSetAttribute(k_p1, cudaFuncAttributeMaxDynamicSharedMemorySize, 49152);
    cudaFuncSetAttribute(k_p2, cudaFuncAttributeMaxDynamicSharedMemorySize, 36864);
    cudaFuncSetAttribute(k_p3, cudaFuncAttributeMaxDynamicSharedMemorySize, 36864);
    cudaFuncSetAttribute(k_p4, cudaFuncAttributeMaxDynamicSharedMemorySize, 49152);

    k_prep<<<3200, 256>>>(hidden, queries, combiners);
    k_p1<<<dim3(3, 1, 64), 256, 49152>>>();
    k_p2<<<dim3(2, 4, 32), 256, 36864>>>();
    k_p3<<<dim3(2, 4, 16), 256, 36864>>>();
    k_p4<<<dim3(16, 2, 8), 256, 49152>>>(out);
}